// round 1
// baseline (speedup 1.0000x reference)
#include <cuda_runtime.h>
#include <math.h>

// ---------------------------------------------------------------------------
// Problem constants (match reference)
// ---------------------------------------------------------------------------
#define NB      8192      // batch
#define ND      64        // embedding dim
#define NNEG    128       // negatives per sample
#define KNBR    32        // item-item neighbors

#define W1c     1e-6f
#define W2c     1.0f
#define W3c     1e-6f
#define W4c     1.0f
#define NEG_WEIGHTc 200.0f
#define GAMMAc  1e-4f
#define LAMBDAc 2.5f

#define NORM_BLOCKS 2048
#define NORM_THREADS 256

// ---------------------------------------------------------------------------
// Scratch (device globals -> no allocation inside kernel_launch)
// ---------------------------------------------------------------------------
__device__ float g_norm_partial[NORM_BLOCKS];
__device__ float g_lossL[NB];
__device__ float g_lossI[NB];
__device__ float g_mseP[NB];

__device__ __forceinline__ float softplusf(float x) {
    // log(1+e^x), numerically stable
    return fmaxf(x, 0.0f) + log1pf(expf(-fabsf(x)));
}

// ---------------------------------------------------------------------------
// Kernel 1: sum of squares over all learned params
// ---------------------------------------------------------------------------
struct NormArgs {
    const float* big0; long n0;   // user_emb (U*D)
    const float* big1; long n1;   // item_emb (I*D)
    const float* sp[8]; int sn[8];// the 8 small param tensors
};

__global__ void __launch_bounds__(NORM_THREADS)
norm_kernel(NormArgs a) {
    float acc = 0.0f;
    size_t tid = (size_t)blockIdx.x * blockDim.x + threadIdx.x;
    size_t stride = (size_t)gridDim.x * blockDim.x;

    const float4* p0 = (const float4*)a.big0;
    size_t m0 = (size_t)a.n0 >> 2;
    for (size_t i = tid; i < m0; i += stride) {
        float4 v = p0[i];
        acc += v.x*v.x + v.y*v.y + v.z*v.z + v.w*v.w;
    }
    const float4* p1 = (const float4*)a.big1;
    size_t m1 = (size_t)a.n1 >> 2;
    for (size_t i = tid; i < m1; i += stride) {
        float4 v = p1[i];
        acc += v.x*v.x + v.y*v.y + v.z*v.z + v.w*v.w;
    }
    #pragma unroll
    for (int j = 0; j < 8; j++) {
        const float* q = a.sp[j];
        int n = a.sn[j];
        for (int i = (int)tid; i < n; i += (int)stride) {
            float v = q[i];
            acc += v * v;
        }
    }

    // warp reduce
    #pragma unroll
    for (int o = 16; o; o >>= 1) acc += __shfl_xor_sync(0xFFFFFFFFu, acc, o);
    __shared__ float sred[NORM_THREADS / 32];
    if ((threadIdx.x & 31) == 0) sred[threadIdx.x >> 5] = acc;
    __syncthreads();
    if (threadIdx.x == 0) {
        float v = 0.0f;
        #pragma unroll
        for (int w = 0; w < NORM_THREADS / 32; w++) v += sred[w];
        g_norm_partial[blockIdx.x] = v;
    }
}

// ---------------------------------------------------------------------------
// Kernel 2: per-sample loss_L / loss_I / mse partials. One CTA per sample.
// 256 threads = 8 warps. Each warp: 16 negatives + 4 neighbors.
// ---------------------------------------------------------------------------
__global__ void __launch_bounds__(256)
sample_kernel(const int*   __restrict__ users,
              const int*   __restrict__ pos_items,
              const int*   __restrict__ neg_items,
              const float* __restrict__ rpkms,
              const float* __restrict__ user_emb,
              const float* __restrict__ item_emb,
              const float* __restrict__ beta_uD,
              const float* __restrict__ beta_iD,
              const int*   __restrict__ ii_nbr,
              const float* __restrict__ ii_con,
              const float* __restrict__ mse_u_w,
              const float* __restrict__ mse_u_b,
              const float* __restrict__ mse_i_w,
              const float* __restrict__ mse_i_b)
{
    const int b = blockIdx.x;
    const int tid = threadIdx.x;
    const int lane = tid & 31;
    const int warp = tid >> 5;

    __shared__ float s_ue[ND];
    __shared__ float s_pe[ND];
    __shared__ float s_feat[2 * ND];
    __shared__ float sN[8], sI[8];
    __shared__ float sPosLoss, sMse;

    const int u = users[b];
    const int p = pos_items[b];

    if (tid < ND)          s_ue[tid]       = user_emb[(size_t)u * ND + tid];
    else if (tid < 2 * ND) s_pe[tid - ND]  = item_emb[(size_t)p * ND + (tid - ND)];
    __syncthreads();

    const float bu = beta_uD[u];
    const float2 uev = make_float2(s_ue[2 * lane], s_ue[2 * lane + 1]);

    // ---- negatives: warp handles 16, unrolled by 2 for MLP ----
    float accN = 0.0f;
    const int* negb = neg_items + (size_t)b * NNEG + warp * 16;
    #pragma unroll
    for (int n = 0; n < 16; n += 2) {
        const int i0 = negb[n];
        const int i1 = negb[n + 1];
        const float bi0 = beta_iD[i0];
        const float bi1 = beta_iD[i1];
        const float2 v0 = ((const float2*)(item_emb + (size_t)i0 * ND))[lane];
        const float2 v1 = ((const float2*)(item_emb + (size_t)i1 * ND))[lane];
        float s0 = v0.x * uev.x + v0.y * uev.y;
        float s1 = v1.x * uev.x + v1.y * uev.y;
        #pragma unroll
        for (int o = 16; o; o >>= 1) {
            s0 += __shfl_xor_sync(0xFFFFFFFFu, s0, o);
            s1 += __shfl_xor_sync(0xFFFFFFFFu, s1, o);
        }
        const float w0 = W3c + W4c * bu * bi0;
        const float w1 = W3c + W4c * bu * bi1;
        accN += w0 * softplusf(s0) + w1 * softplusf(s1);
    }

    // ---- neighbors: warp handles 4, unrolled by 2 ----
    float accI = 0.0f;
    const int*   nbrp = ii_nbr + (size_t)p * KNBR + warp * 4;
    const float* simp = ii_con + (size_t)p * KNBR + warp * 4;
    #pragma unroll
    for (int k = 0; k < 4; k += 2) {
        const int j0 = nbrp[k];
        const int j1 = nbrp[k + 1];
        const float c0 = simp[k];
        const float c1 = simp[k + 1];
        const float2 v0 = ((const float2*)(item_emb + (size_t)j0 * ND))[lane];
        const float2 v1 = ((const float2*)(item_emb + (size_t)j1 * ND))[lane];
        float s0 = v0.x * uev.x + v0.y * uev.y;
        float s1 = v1.x * uev.x + v1.y * uev.y;
        #pragma unroll
        for (int o = 16; o; o >>= 1) {
            s0 += __shfl_xor_sync(0xFFFFFFFFu, s0, o);
            s1 += __shfl_xor_sync(0xFFFFFFFFu, s1, o);
        }
        accI += c0 * softplusf(-s0) + c1 * softplusf(-s1);
    }

    if (lane == 0) { sN[warp] = accN; sI[warp] = accI; }

    // ---- positive score (warp 0) ----
    if (warp == 0) {
        const float2 pv = make_float2(s_pe[2 * lane], s_pe[2 * lane + 1]);
        float s = pv.x * uev.x + pv.y * uev.y;
        #pragma unroll
        for (int o = 16; o; o >>= 1) s += __shfl_xor_sync(0xFFFFFFFFu, s, o);
        if (lane == 0) {
            const float bip = beta_iD[p];
            const float pw = W1c + W2c * bu * bip;
            sPosLoss = pw * softplusf(-s);
        }
    }

    // ---- MSE features: feat[d] = b[d] + sum_j W[d][j] * e[j] ----
    if (tid < ND) {
        float acc = mse_u_b[tid];
        const float* wr = mse_u_w + tid * ND;
        #pragma unroll 8
        for (int j = 0; j < ND; j++) acc = fmaf(__ldg(wr + j), s_ue[j], acc);
        s_feat[tid] = acc;
    } else if (tid < 2 * ND) {
        const int d = tid - ND;
        float acc = mse_i_b[d];
        const float* wr = mse_i_w + d * ND;
        #pragma unroll 8
        for (int j = 0; j < ND; j++) acc = fmaf(__ldg(wr + j), s_pe[j], acc);
        s_feat[ND + d] = acc;
    }
    __syncthreads();

    if (warp == 1) {
        const float2 fu = ((const float2*)(s_feat))[lane];
        const float2 fi = ((const float2*)(s_feat + ND))[lane];
        float s = fu.x * fi.x + fu.y * fi.y;
        #pragma unroll
        for (int o = 16; o; o >>= 1) s += __shfl_xor_sync(0xFFFFFFFFu, s, o);
        if (lane == 0) {
            const float dlt = s - rpkms[b];
            sMse = dlt * dlt;
        }
    }
    __syncthreads();

    if (tid == 0) {
        float sn = 0.0f, si = 0.0f;
        #pragma unroll
        for (int w = 0; w < 8; w++) { sn += sN[w]; si += sI[w]; }
        g_lossL[b] = sPosLoss + NEG_WEIGHTc * (sn * (1.0f / NNEG));
        g_lossI[b] = si;
        g_mseP[b]  = sMse;
    }
}

// ---------------------------------------------------------------------------
// Kernel 3: deterministic final reduction -> 6 outputs
// ---------------------------------------------------------------------------
__global__ void __launch_bounds__(256)
finalize_kernel(float* __restrict__ out) {
    const int tid = threadIdx.x;
    double aL = 0.0, aI = 0.0, aM = 0.0, aN = 0.0;
    for (int i = tid; i < NB; i += 256) {
        aL += (double)g_lossL[i];
        aI += (double)g_lossI[i];
        aM += (double)g_mseP[i];
    }
    for (int i = tid; i < NORM_BLOCKS; i += 256) aN += (double)g_norm_partial[i];

    __shared__ double rL[256], rI[256], rM[256], rN[256];
    rL[tid] = aL; rI[tid] = aI; rM[tid] = aM; rN[tid] = aN;
    __syncthreads();
    for (int o = 128; o; o >>= 1) {
        if (tid < o) {
            rL[tid] += rL[tid + o];
            rI[tid] += rI[tid + o];
            rM[tid] += rM[tid + o];
            rN[tid] += rN[tid + o];
        }
        __syncthreads();
    }
    if (tid == 0) {
        const double lossL = rL[0] / (double)NB;
        const double lossI = rI[0] * ((double)LAMBDAc / ((double)NB * (double)KNBR));
        const double mse   = rM[0] / (double)NB;
        const double norm  = rN[0] * 0.5 * (double)GAMMAc;
        out[0] = (float)(lossL + lossI + mse + norm);
        out[1] = (float)lossL;
        out[2] = (float)lossI;
        out[3] = 0.0f;
        out[4] = (float)mse;
        out[5] = (float)norm;
    }
}

// ---------------------------------------------------------------------------
// Launch. Input order per metadata (reference signature order):
//  0 users(i32,B) 1 pos_items(i32,B) 2 neg_items(i32,B*NNEG) 3 rpkms(f32,B)
//  4 user_emb(f32,U*D) 5 item_emb(f32,I*D) 6 beta_uD(f32,U) 7 beta_iD(f32,I)
//  8 ii_neighbor_mat(i32,I*K) 9 ii_constraint_mat(f32,I*K)
// 10 mse_u_w(f32,D*D) 11 mse_u_b(f32,D) 12 mse_i_w(f32,D*D) 13 mse_i_b(f32,D)
// 14 fc1_w1(f32,D*2D) 15 fc1_b1(f32,D) 16 fc1_w2(f32,D) 17 fc1_b2(f32,1)
// ---------------------------------------------------------------------------
extern "C" void kernel_launch(void* const* d_in, const int* in_sizes, int n_in,
                              void* d_out, int out_size) {
    const int*   users     = (const int*)d_in[0];
    const int*   pos_items = (const int*)d_in[1];
    const int*   neg_items = (const int*)d_in[2];
    const float* rpkms     = (const float*)d_in[3];
    const float* user_emb  = (const float*)d_in[4];
    const float* item_emb  = (const float*)d_in[5];
    const float* beta_uD   = (const float*)d_in[6];
    const float* beta_iD   = (const float*)d_in[7];
    const int*   ii_nbr    = (const int*)d_in[8];
    const float* ii_con    = (const float*)d_in[9];
    const float* mse_u_w   = (const float*)d_in[10];
    const float* mse_u_b   = (const float*)d_in[11];
    const float* mse_i_w   = (const float*)d_in[12];
    const float* mse_i_b   = (const float*)d_in[13];
    const float* fc1_w1    = (const float*)d_in[14];
    const float* fc1_b1    = (const float*)d_in[15];
    const float* fc1_w2    = (const float*)d_in[16];
    const float* fc1_b2    = (const float*)d_in[17];

    NormArgs na;
    na.big0 = user_emb; na.n0 = in_sizes[4];
    na.big1 = item_emb; na.n1 = in_sizes[5];
    na.sp[0] = mse_u_w; na.sn[0] = in_sizes[10];
    na.sp[1] = mse_u_b; na.sn[1] = in_sizes[11];
    na.sp[2] = mse_i_w; na.sn[2] = in_sizes[12];
    na.sp[3] = mse_i_b; na.sn[3] = in_sizes[13];
    na.sp[4] = fc1_w1;  na.sn[4] = in_sizes[14];
    na.sp[5] = fc1_b1;  na.sn[5] = in_sizes[15];
    na.sp[6] = fc1_w2;  na.sn[6] = in_sizes[16];
    na.sp[7] = fc1_b2;  na.sn[7] = in_sizes[17];

    norm_kernel<<<NORM_BLOCKS, NORM_THREADS>>>(na);

    sample_kernel<<<NB, 256>>>(users, pos_items, neg_items, rpkms,
                               user_emb, item_emb, beta_uD, beta_iD,
                               ii_nbr, ii_con,
                               mse_u_w, mse_u_b, mse_i_w, mse_i_b);

    finalize_kernel<<<1, 256>>>((float*)d_out);
}

// round 2
// speedup vs baseline: 2.4504x; 2.4504x over previous
#include <cuda_runtime.h>
#include <math.h>

// ---------------------------------------------------------------------------
// Problem constants
// ---------------------------------------------------------------------------
#define NB      8192
#define ND      64
#define NNEG    128
#define KNBR    32

#define W1c     1e-6f
#define W3c     1e-6f
#define NEG_WEIGHTc 200.0f
#define GAMMAc  1e-4f
#define LAMBDAc 2.5f

// ---------------------------------------------------------------------------
// Scratch (device globals)
// ---------------------------------------------------------------------------
__device__ float g_M[ND * ND];     // M = W_u^T W_i
__device__ float g_cpe[ND];        // W_i^T b_u
__device__ float g_cue[ND];        // W_u^T b_i
__device__ float g_c0;             // b_u . b_i
__device__ float g_norm_partial[NB];
__device__ float g_lossL[NB];
__device__ float g_lossI[NB];
__device__ float g_mseP[NB];

__device__ __forceinline__ float softplusf(float x) {
    return fmaxf(x, 0.0f) + __logf(1.0f + __expf(-fabsf(x)));
}

__device__ __forceinline__ float bfly(float s) {
    #pragma unroll
    for (int o = 16; o; o >>= 1) s += __shfl_xor_sync(0xFFFFFFFFu, s, o);
    return s;
}

// ---------------------------------------------------------------------------
// Kernel 1: precompute M = W_u^T W_i  (and bias terms)
// grid 16 x 256 : one thread per M entry
// ---------------------------------------------------------------------------
__global__ void __launch_bounds__(256)
precompute_kernel(const float* __restrict__ wu, const float* __restrict__ bu,
                  const float* __restrict__ wi, const float* __restrict__ bi) {
    const int idx = blockIdx.x * 256 + threadIdx.x;
    const int a = idx >> 6;     // row of M
    const int c = idx & 63;     // col of M
    float acc = 0.0f;
    #pragma unroll 8
    for (int d = 0; d < ND; d++)
        acc = fmaf(wu[d * ND + a], wi[d * ND + c], acc);
    g_M[idx] = acc;

    if (blockIdx.x == 0) {
        if (threadIdx.x < ND) {
            const int j = threadIdx.x;
            float c1 = 0.0f, c2 = 0.0f;
            #pragma unroll 8
            for (int d = 0; d < ND; d++) {
                c1 = fmaf(wi[d * ND + j], bu[d], c1);
                c2 = fmaf(wu[d * ND + j], bi[d], c2);
            }
            g_cpe[j] = c1;
            g_cue[j] = c2;
            if (j == 0) {
                float s = 0.0f;
                #pragma unroll 8
                for (int d = 0; d < ND; d++) s = fmaf(bu[d], bi[d], s);
                g_c0 = s;
            }
        }
    }
}

// ---------------------------------------------------------------------------
// Fused kernel args
// ---------------------------------------------------------------------------
struct FusedArgs {
    const int*   users;
    const int*   pos_items;
    const int*   neg_items;
    const float* rpkms;
    const float* user_emb;  long nu;   // element count
    const float* item_emb;  long ni;
    const float* beta_uD;
    const float* beta_iD;
    const int*   ii_nbr;
    const float* ii_con;
    const float* sp[8]; int sn[8];     // 8 small param tensors for norm
};

// ---------------------------------------------------------------------------
// norm slice: grid-stride sum of squares over both big tables (+ small params
// handled by CTA 0)
// ---------------------------------------------------------------------------
__device__ __forceinline__ float norm_slice(const FusedArgs& a) {
    float acc = 0.0f;
    const size_t tg = (size_t)blockIdx.x * 256 + threadIdx.x;
    const size_t stride = (size_t)gridDim.x * 256;

    const float4* pu = (const float4*)a.user_emb;
    const size_t mu = (size_t)a.nu >> 2;
    for (size_t i = tg; i < mu; i += stride) {
        float4 v = pu[i];
        acc += v.x*v.x + v.y*v.y + v.z*v.z + v.w*v.w;
    }
    const float4* pi = (const float4*)a.item_emb;
    const size_t mi = (size_t)a.ni >> 2;
    for (size_t i = tg; i < mi; i += stride) {
        float4 v = pi[i];
        acc += v.x*v.x + v.y*v.y + v.z*v.z + v.w*v.w;
    }
    if (blockIdx.x == 0) {
        #pragma unroll
        for (int j = 0; j < 8; j++) {
            const float* q = a.sp[j];
            const int n = a.sn[j];
            for (int i = threadIdx.x; i < n; i += 256) {
                float v = q[i];
                acc += v * v;
            }
        }
    }
    return acc;
}

// ---------------------------------------------------------------------------
// per-sample work (one CTA = one sample). Assumes s_ue/s_pe preloaded + synced.
// ---------------------------------------------------------------------------
__device__ __forceinline__ void sample_work(
    const FusedArgs& a, int b, int u, int p,
    const float* s_ue, const float* s_pe, float* s_t,
    float* sN, float* sI, float* sPosLoss, float* sMse)
{
    const int tid  = threadIdx.x;
    const int lane = tid & 31;
    const int warp = tid >> 5;

    const float  bu  = __ldg(a.beta_uD + u);
    const float2 uev = make_float2(s_ue[2 * lane], s_ue[2 * lane + 1]);

    // ---- negatives: warp handles 16, unroll 4 (MLP=4, ILP'd shuffles) ----
    float accN = 0.0f;
    const int* negb = a.neg_items + (size_t)b * NNEG + warp * 16;
    #pragma unroll
    for (int n = 0; n < 16; n += 4) {
        const int i0 = negb[n + 0];
        const int i1 = negb[n + 1];
        const int i2 = negb[n + 2];
        const int i3 = negb[n + 3];
        const float2 v0 = __ldg((const float2*)(a.item_emb + (size_t)i0 * ND) + lane);
        const float2 v1 = __ldg((const float2*)(a.item_emb + (size_t)i1 * ND) + lane);
        const float2 v2 = __ldg((const float2*)(a.item_emb + (size_t)i2 * ND) + lane);
        const float2 v3 = __ldg((const float2*)(a.item_emb + (size_t)i3 * ND) + lane);
        const float bi0 = __ldg(a.beta_iD + i0);
        const float bi1 = __ldg(a.beta_iD + i1);
        const float bi2 = __ldg(a.beta_iD + i2);
        const float bi3 = __ldg(a.beta_iD + i3);
        float s0 = fmaf(v0.x, uev.x, v0.y * uev.y);
        float s1 = fmaf(v1.x, uev.x, v1.y * uev.y);
        float s2 = fmaf(v2.x, uev.x, v2.y * uev.y);
        float s3 = fmaf(v3.x, uev.x, v3.y * uev.y);
        #pragma unroll
        for (int o = 16; o; o >>= 1) {
            s0 += __shfl_xor_sync(0xFFFFFFFFu, s0, o);
            s1 += __shfl_xor_sync(0xFFFFFFFFu, s1, o);
            s2 += __shfl_xor_sync(0xFFFFFFFFu, s2, o);
            s3 += __shfl_xor_sync(0xFFFFFFFFu, s3, o);
        }
        accN += fmaf(bu, bi0, W3c) * softplusf(s0)
              + fmaf(bu, bi1, W3c) * softplusf(s1)
              + fmaf(bu, bi2, W3c) * softplusf(s2)
              + fmaf(bu, bi3, W3c) * softplusf(s3);
    }

    // ---- neighbors: warp handles 4, fully unrolled ----
    float accI = 0.0f;
    {
        const int*   nbrp = a.ii_nbr + (size_t)p * KNBR + warp * 4;
        const float* simp = a.ii_con + (size_t)p * KNBR + warp * 4;
        const int j0 = nbrp[0];
        const int j1 = nbrp[1];
        const int j2 = nbrp[2];
        const int j3 = nbrp[3];
        const float2 v0 = __ldg((const float2*)(a.item_emb + (size_t)j0 * ND) + lane);
        const float2 v1 = __ldg((const float2*)(a.item_emb + (size_t)j1 * ND) + lane);
        const float2 v2 = __ldg((const float2*)(a.item_emb + (size_t)j2 * ND) + lane);
        const float2 v3 = __ldg((const float2*)(a.item_emb + (size_t)j3 * ND) + lane);
        float s0 = fmaf(v0.x, uev.x, v0.y * uev.y);
        float s1 = fmaf(v1.x, uev.x, v1.y * uev.y);
        float s2 = fmaf(v2.x, uev.x, v2.y * uev.y);
        float s3 = fmaf(v3.x, uev.x, v3.y * uev.y);
        #pragma unroll
        for (int o = 16; o; o >>= 1) {
            s0 += __shfl_xor_sync(0xFFFFFFFFu, s0, o);
            s1 += __shfl_xor_sync(0xFFFFFFFFu, s1, o);
            s2 += __shfl_xor_sync(0xFFFFFFFFu, s2, o);
            s3 += __shfl_xor_sync(0xFFFFFFFFu, s3, o);
        }
        accI += simp[0] * softplusf(-s0) + simp[1] * softplusf(-s1)
              + simp[2] * softplusf(-s2) + simp[3] * softplusf(-s3);
    }

    if (lane == 0) { sN[warp] = accN; sI[warp] = accI; }

    // ---- matvec t = M^T ue (+cpe) : coalesced over 64 threads ----
    if (tid < ND) {
        float acc = g_cpe[tid];
        #pragma unroll 16
        for (int d = 0; d < ND; d++)
            acc = fmaf(s_ue[d], g_M[d * ND + tid], acc);
        s_t[tid] = acc;
    }

    // ---- positive score (warp 2, concurrent with matvec) ----
    if (warp == 2) {
        const float2 pv = make_float2(s_pe[2 * lane], s_pe[2 * lane + 1]);
        float s = fmaf(pv.x, uev.x, pv.y * uev.y);
        s = bfly(s);
        if (lane == 0) {
            const float bip = __ldg(a.beta_iD + p);
            *sPosLoss = fmaf(bu, bip, W1c) * softplusf(-s);
        }
    }
    __syncthreads();

    // ---- mse (warp 0) ----
    if (warp == 0) {
        float v = s_t[2*lane] * s_pe[2*lane] + s_t[2*lane+1] * s_pe[2*lane+1]
                + g_cue[2*lane] * s_ue[2*lane] + g_cue[2*lane+1] * s_ue[2*lane+1];
        v = bfly(v);
        if (lane == 0) {
            const float pred = v + g_c0;
            const float dlt = pred - __ldg(a.rpkms + b);
            *sMse = dlt * dlt;
        }
    }
    __syncthreads();

    if (tid == 0) {
        float sn = 0.0f, si = 0.0f;
        #pragma unroll
        for (int w = 0; w < 8; w++) { sn += sN[w]; si += sI[w]; }
        g_lossL[b] = *sPosLoss + NEG_WEIGHTc * (sn * (1.0f / NNEG));
        g_lossI[b] = si;
        g_mseP[b]  = *sMse;
    }
}

// ---------------------------------------------------------------------------
// Fused kernel: one CTA per sample + grid-stride norm slice.
// CTA parity alternates ordering so gathers overlap streaming chip-wide.
// ---------------------------------------------------------------------------
__global__ void __launch_bounds__(256)
fused_kernel(FusedArgs a) {
    const int b = blockIdx.x;
    const int tid = threadIdx.x;

    __shared__ float s_ue[ND];
    __shared__ float s_pe[ND];
    __shared__ float s_t[ND];
    __shared__ float sN[8], sI[8];
    __shared__ float sPosLoss, sMse;
    __shared__ float sNorm[8];

    const int u = __ldg(a.users + b);
    const int p = __ldg(a.pos_items + b);
    if (tid < ND)          s_ue[tid]      = __ldg(a.user_emb + (size_t)u * ND + tid);
    else if (tid < 2 * ND) s_pe[tid - ND] = __ldg(a.item_emb + (size_t)p * ND + (tid - ND));
    __syncthreads();

    float nacc;
    if (b & 1) {
        nacc = norm_slice(a);
        sample_work(a, b, u, p, s_ue, s_pe, s_t, sN, sI, &sPosLoss, &sMse);
    } else {
        sample_work(a, b, u, p, s_ue, s_pe, s_t, sN, sI, &sPosLoss, &sMse);
        nacc = norm_slice(a);
    }

    // CTA-reduce the norm partial
    nacc = bfly(nacc);
    if ((tid & 31) == 0) sNorm[tid >> 5] = nacc;
    __syncthreads();
    if (tid == 0) {
        float v = 0.0f;
        #pragma unroll
        for (int w = 0; w < 8; w++) v += sNorm[w];
        g_norm_partial[b] = v;
    }
}

// ---------------------------------------------------------------------------
// Finalize: deterministic reduction -> 6 outputs
// ---------------------------------------------------------------------------
__global__ void __launch_bounds__(256)
finalize_kernel(float* __restrict__ out) {
    const int tid = threadIdx.x;
    double aL = 0.0, aI = 0.0, aM = 0.0, aN = 0.0;
    for (int i = tid; i < NB; i += 256) {
        aL += (double)g_lossL[i];
        aI += (double)g_lossI[i];
        aM += (double)g_mseP[i];
        aN += (double)g_norm_partial[i];
    }
    __shared__ double rL[256], rI[256], rM[256], rN[256];
    rL[tid] = aL; rI[tid] = aI; rM[tid] = aM; rN[tid] = aN;
    __syncthreads();
    for (int o = 128; o; o >>= 1) {
        if (tid < o) {
            rL[tid] += rL[tid + o];
            rI[tid] += rI[tid + o];
            rM[tid] += rM[tid + o];
            rN[tid] += rN[tid + o];
        }
        __syncthreads();
    }
    if (tid == 0) {
        const double lossL = rL[0] / (double)NB;
        const double lossI = rI[0] * ((double)LAMBDAc / ((double)NB * (double)KNBR));
        const double mse   = rM[0] / (double)NB;
        const double norm  = rN[0] * 0.5 * (double)GAMMAc;
        out[0] = (float)(lossL + lossI + mse + norm);
        out[1] = (float)lossL;
        out[2] = (float)lossI;
        out[3] = 0.0f;
        out[4] = (float)mse;
        out[5] = (float)norm;
    }
}

// ---------------------------------------------------------------------------
// Launch
// ---------------------------------------------------------------------------
extern "C" void kernel_launch(void* const* d_in, const int* in_sizes, int n_in,
                              void* d_out, int out_size) {
    FusedArgs a;
    a.users     = (const int*)d_in[0];
    a.pos_items = (const int*)d_in[1];
    a.neg_items = (const int*)d_in[2];
    a.rpkms     = (const float*)d_in[3];
    a.user_emb  = (const float*)d_in[4];  a.nu = in_sizes[4];
    a.item_emb  = (const float*)d_in[5];  a.ni = in_sizes[5];
    a.beta_uD   = (const float*)d_in[6];
    a.beta_iD   = (const float*)d_in[7];
    a.ii_nbr    = (const int*)d_in[8];
    a.ii_con    = (const float*)d_in[9];
    const float* mse_u_w = (const float*)d_in[10];
    const float* mse_u_b = (const float*)d_in[11];
    const float* mse_i_w = (const float*)d_in[12];
    const float* mse_i_b = (const float*)d_in[13];
    a.sp[0] = mse_u_w;               a.sn[0] = in_sizes[10];
    a.sp[1] = mse_u_b;               a.sn[1] = in_sizes[11];
    a.sp[2] = mse_i_w;               a.sn[2] = in_sizes[12];
    a.sp[3] = mse_i_b;               a.sn[3] = in_sizes[13];
    a.sp[4] = (const float*)d_in[14]; a.sn[4] = in_sizes[14];
    a.sp[5] = (const float*)d_in[15]; a.sn[5] = in_sizes[15];
    a.sp[6] = (const float*)d_in[16]; a.sn[6] = in_sizes[16];
    a.sp[7] = (const float*)d_in[17]; a.sn[7] = in_sizes[17];

    precompute_kernel<<<16, 256>>>(mse_u_w, mse_u_b, mse_i_w, mse_i_b);
    fused_kernel<<<NB, 256>>>(a);
    finalize_kernel<<<1, 256>>>((float*)d_out);
}